// round 14
// baseline (speedup 1.0000x reference)
#include <cuda_runtime.h>
#include <math.h>

#define GCTA    64
#define RTHREADS 512
#define JPC     8
#define T_STEPS 2048
#define BATCH   32
#define HDIM    512
#define DIN     256

// ---- scratch (device globals; no allocation allowed) ----
__device__ float g_xw[(size_t)T_STEPS * HDIM * BATCH];   // [t][j][b], 134MB
__device__ float g_h[2][HDIM * BATCH];                   // ping-pong hidden state, [j][b]
__device__ float g_qh[BATCH * HDIM];                     // KW @ Q0
__device__ float g_sc[BATCH * T_STEPS];                  // scores
__device__ float g_att[BATCH * T_STEPS];                 // softmax weights
__device__ float g_cpart[8][BATCH * HDIM];               // context partials
__device__ __align__(128) unsigned g_flag[GCTA * 32];    // per-CTA arrive flags, 128B apart

// ---------------------------------------------------------------------------
__global__ void init_kernel() {
    int idx = blockIdx.x * blockDim.x + threadIdx.x;
    if (idx < HDIM * BATCH) g_h[0][idx] = 0.f;
    if (idx < GCTA) g_flag[idx * 32] = 0u;
}

__global__ void dummy_kernel() {}   // launch-position filler so ncu -s 5 lands on rnn_loop

// ---------------------------------------------------------------------------
// xw[t][j][b] = sum_d X[b][t][d] * Wxh[d][j]
__global__ __launch_bounds__(256) void xw_kernel(const float* __restrict__ X,
                                                 const float* __restrict__ Wxh) {
    __shared__ __align__(16) float Xs[128 * 33];  // [dl][b], padded
    __shared__ __align__(16) float Ws[128 * 32];  // [dl][jj]
    int t  = blockIdx.x;
    int j0 = blockIdx.y * 32;
    int tid = threadIdx.x;
    int warp = tid >> 5, lane = tid & 31;
    float acc0 = 0.f, acc1 = 0.f, acc2 = 0.f, acc3 = 0.f;

    for (int kp = 0; kp < 2; ++kp) {
        #pragma unroll
        for (int bb = 0; bb < 4; ++bb) {
            int b = warp * 4 + bb;
            const float* xp = X + ((size_t)b * T_STEPS + t) * DIN + kp * 128;
            #pragma unroll
            for (int it = 0; it < 4; ++it) {
                int dl = it * 32 + lane;
                Xs[dl * 33 + b] = xp[dl];
            }
        }
        for (int idx = tid; idx < 128 * 32; idx += 256) {
            int dl = idx >> 5, jj = idx & 31;
            Ws[idx] = Wxh[(size_t)(kp * 128 + dl) * HDIM + j0 + jj];
        }
        __syncthreads();
        #pragma unroll 8
        for (int dl = 0; dl < 128; ++dl) {
            float xv = Xs[dl * 33 + lane];
            float4 w = *(const float4*)&Ws[dl * 32 + warp * 4];
            acc0 += xv * w.x; acc1 += xv * w.y; acc2 += xv * w.z; acc3 += xv * w.w;
        }
        __syncthreads();
    }
    float* op = g_xw + ((size_t)t * HDIM + j0 + warp * 4) * BATCH + lane;
    op[0]  = acc0;
    op[32] = acc1;
    op[64] = acc2;
    op[96] = acc3;
}

// ---------------------------------------------------------------------------
// Persistent recurrence, SELF-TIMED chunked dataflow. 64 CTAs x 512 threads;
// CTA owns 8 consecutive j's (one "chunk"). No global detect-all phase: each
// of the 16 warps owns 4 producer chunks and consumes each as soon as that
// producer's flag shows step t — straggler latency overlaps with compute on
// already-arrived chunks. Reduction syncthreads absorbs residual skew.
__global__ __launch_bounds__(RTHREADS) void rnn_loop(const float* __restrict__ Whh,
                                                     const float* __restrict__ bh,
                                                     float* __restrict__ Y) {
    __shared__ __align__(16) float Ws[HDIM * JPC];        // [i][c], c=0..7, 16KB
    __shared__ __align__(16) float red[JPC * RTHREADS];   // [c][warp][lane], 16KB
    __shared__ float stage[32 * 9];                       // h_out staged [b][c]
    int g   = blockIdx.x;
    int j0  = g * JPC;
    int tid = threadIdx.x;
    for (int idx = tid; idx < HDIM * JPC; idx += RTHREADS) {
        int i = idx >> 3, c = idx & 7;
        Ws[idx] = Whh[(size_t)i * HDIM + j0 + c];
    }
    int rb = tid & 31, rc = tid >> 5;          // reducer mapping (tid < 256): b, c
    int sb = tid >> 3, sc = tid & 7;           // Y-writer mapping (tid < 256): b, c
    float bias = (tid < 256) ? bh[j0 + rc] : 0.f;
    int warp = tid >> 5, lane = tid & 31;
    int c0 = (g + 1 + warp) & 63;              // this warp's first chunk (rotated)
    unsigned* myflag = &g_flag[g * 32];
    __syncthreads();

    float xw_pref = (tid < 256) ? g_xw[((size_t)0 * HDIM + j0 + rc) * BATCH + rb] : 0.f;

    for (int t = 0; t < T_STEPS; ++t) {
        const float* hin = g_h[t & 1];
        float* hout = g_h[(t & 1) ^ 1];
        unsigned long long a01 = 0ull, a23 = 0ull, a45 = 0ull, a67 = 0ull;

        // ---- consume 4 chunks as their producers publish step t ----
        #pragma unroll
        for (int k = 0; k < 4; ++k) {
            int r = (c0 + k * 16) & 63;
            if (t > 0) {                       // step 0: h is pre-initialized zeros
                unsigned tgt = (unsigned)t, v;
                unsigned* fp = &g_flag[r * 32];
                do { asm volatile("ld.relaxed.gpu.global.u32 %0, [%1];"
                                  : "=r"(v) : "l"(fp)); } while (v < tgt);
                asm volatile("fence.acq_rel.gpu;" ::: "memory");
            }
            const float* hp = hin + (r * JPC) * BATCH + lane;   // coalesced rows
            #pragma unroll
            for (int q = 0; q < 8; ++q) {
                float hv = __ldcg(hp + q * BATCH);
                unsigned long long hv2;
                asm("mov.b64 %0, {%1, %1};" : "=l"(hv2) : "f"(hv));
                ulonglong2 wA = *(const ulonglong2*)&Ws[(r * JPC + q) * JPC];
                ulonglong2 wB = *(const ulonglong2*)&Ws[(r * JPC + q) * JPC + 4];
                asm("fma.rn.f32x2 %0, %1, %2, %0;" : "+l"(a01) : "l"(hv2), "l"(wA.x));
                asm("fma.rn.f32x2 %0, %1, %2, %0;" : "+l"(a23) : "l"(hv2), "l"(wA.y));
                asm("fma.rn.f32x2 %0, %1, %2, %0;" : "+l"(a45) : "l"(hv2), "l"(wB.x));
                asm("fma.rn.f32x2 %0, %1, %2, %0;" : "+l"(a67) : "l"(hv2), "l"(wB.y));
            }
        }
        {   // unpack partials into smem (conflict-free: red[c][warp][lane])
            float p0,p1,p2,p3,p4,p5,p6,p7;
            asm("mov.b64 {%0, %1}, %2;" : "=f"(p0), "=f"(p1) : "l"(a01));
            asm("mov.b64 {%0, %1}, %2;" : "=f"(p2), "=f"(p3) : "l"(a23));
            asm("mov.b64 {%0, %1}, %2;" : "=f"(p4), "=f"(p5) : "l"(a45));
            asm("mov.b64 {%0, %1}, %2;" : "=f"(p6), "=f"(p7) : "l"(a67));
            red[0*RTHREADS + tid] = p0; red[1*RTHREADS + tid] = p1;
            red[2*RTHREADS + tid] = p2; red[3*RTHREADS + tid] = p3;
            red[4*RTHREADS + tid] = p4; red[5*RTHREADS + tid] = p5;
            red[6*RTHREADS + tid] = p6; red[7*RTHREADS + tid] = p7;
        }
        __syncthreads();

        if (tid < 256) {
            float s = bias + xw_pref;
            #pragma unroll
            for (int w = 0; w < 16; ++w) s += red[rc * RTHREADS + w * 32 + rb];
            float hv_out = tanhf(s);
            __stcg(&hout[(j0 + rc) * BATCH + rb], hv_out);   // coalesced 128B rows
            stage[rb * 9 + rc] = hv_out;
        }
        __syncthreads();

        // ---- publish own chunk for step t+1 (release covers prior stores) ----
        if (tid == 0) {
            unsigned ep = (unsigned)(t + 1);
            asm volatile("st.release.gpu.global.u32 [%0], %1;"
                         :: "l"(myflag), "r"(ep));
        }

        // ---- off-critical-path: coalesced Y output + xw prefetch for t+1 ----
        if (tid < 256) {
            Y[(size_t)t * (BATCH * HDIM) + (size_t)sb * HDIM + j0 + sc] = stage[sb * 9 + sc];
            if (t + 1 < T_STEPS)
                xw_pref = g_xw[((size_t)(t + 1) * HDIM + j0 + rc) * BATCH + rb];
        }
    }
}

// ---------------------------------------------------------------------------
// Q0[b] = Y[T-1,b] @ QW ; Qh[b] = KW @ Q0[b]   (one CTA per b)
__global__ __launch_bounds__(256) void att_q_kernel(const float* __restrict__ Y,
                                                    const float* __restrict__ QW,
                                                    const float* __restrict__ KW) {
    __shared__ float yT[HDIM];
    __shared__ float q0s[DIN];
    int b = blockIdx.x, tid = threadIdx.x;
    for (int h = tid; h < HDIM; h += 256)
        yT[h] = Y[(size_t)(T_STEPS - 1) * BATCH * HDIM + (size_t)b * HDIM + h];
    __syncthreads();
    float s = 0.f;
    for (int h = 0; h < HDIM; ++h) s += yT[h] * QW[(size_t)h * DIN + tid];
    q0s[tid] = s;
    __syncthreads();
    for (int j = tid; j < HDIM; j += 256) {
        float s2 = 0.f;
        const float* kp = KW + (size_t)j * DIN;
        #pragma unroll 4
        for (int d = 0; d < DIN; ++d) s2 += kp[d] * q0s[d];
        g_qh[b * HDIM + j] = s2;
    }
}

// scores[b][t] = tanh( Y[t,b,:] . Qh[b,:] )
__global__ __launch_bounds__(256) void att_scores_kernel(const float* __restrict__ Y) {
    __shared__ float qh[HDIM];
    int b = blockIdx.y, t0 = blockIdx.x * 64, tid = threadIdx.x;
    for (int h = tid; h < HDIM; h += 256) qh[h] = g_qh[b * HDIM + h];
    __syncthreads();
    int warp = tid >> 5, lane = tid & 31;
    for (int tt = warp; tt < 64; tt += 8) {
        int t = t0 + tt;
        const float* yp = Y + (size_t)t * BATCH * HDIM + (size_t)b * HDIM;
        float s = 0.f;
        #pragma unroll
        for (int it = 0; it < 16; ++it) s += yp[it * 32 + lane] * qh[it * 32 + lane];
        #pragma unroll
        for (int off = 16; off > 0; off >>= 1) s += __shfl_xor_sync(0xffffffffu, s, off);
        if (lane == 0) g_sc[b * T_STEPS + t] = tanhf(s);
    }
}

__global__ __launch_bounds__(256) void att_softmax_kernel() {
    __shared__ float sred[256];
    int b = blockIdx.x, tid = threadIdx.x;
    const float* sp = g_sc + b * T_STEPS;
    float m = -1e30f;
    for (int t = tid; t < T_STEPS; t += 256) m = fmaxf(m, sp[t]);
    sred[tid] = m; __syncthreads();
    for (int o = 128; o > 0; o >>= 1) {
        if (tid < o) sred[tid] = fmaxf(sred[tid], sred[tid + o]);
        __syncthreads();
    }
    m = sred[0]; __syncthreads();
    float sum = 0.f;
    for (int t = tid; t < T_STEPS; t += 256) sum += expf(sp[t] - m);
    sred[tid] = sum; __syncthreads();
    for (int o = 128; o > 0; o >>= 1) {
        if (tid < o) sred[tid] += sred[tid + o];
        __syncthreads();
    }
    float inv = 1.f / sred[0];
    for (int t = tid; t < T_STEPS; t += 256)
        g_att[b * T_STEPS + t] = expf(sp[t] - m) * inv;
}

// c partials: grid (8 t-chunks, 32 b)
__global__ __launch_bounds__(256) void att_ctx_kernel(const float* __restrict__ Y) {
    __shared__ float As[256];
    int tc = blockIdx.x, b = blockIdx.y, tid = threadIdx.x;
    As[tid] = g_att[b * T_STEPS + tc * 256 + tid];
    __syncthreads();
    float acc0 = 0.f, acc1 = 0.f;
    for (int tt = 0; tt < 256; ++tt) {
        const float* yp = Y + (size_t)(tc * 256 + tt) * BATCH * HDIM + (size_t)b * HDIM;
        float a = As[tt];
        acc0 += a * yp[tid];
        acc1 += a * yp[tid + 256];
    }
    g_cpart[tc][b * HDIM + tid]        = acc0;
    g_cpart[tc][b * HDIM + tid + 256]  = acc1;
}

__global__ __launch_bounds__(512) void att_ctx2_kernel(float* __restrict__ out_c) {
    int b = blockIdx.x, tid = threadIdx.x;
    float s = 0.f;
    #pragma unroll
    for (int p = 0; p < 8; ++p) s += g_cpart[p][b * HDIM + tid];
    out_c[(size_t)b * HDIM + tid] = s;
}

// ---------------------------------------------------------------------------
extern "C" void kernel_launch(void* const* d_in, const int* in_sizes, int n_in,
                              void* d_out, int out_size) {
    const float* X   = (const float*)d_in[0];
    const float* Wxh = (const float*)d_in[1];
    const float* Whh = (const float*)d_in[2];
    const float* bh  = (const float*)d_in[3];
    const float* QW  = (const float*)d_in[4];
    const float* KW  = (const float*)d_in[5];
    float* Y = (float*)d_out;                                    // [T][B][H]
    float* out_c = Y + (size_t)T_STEPS * BATCH * HDIM;           // [B][H]

    init_kernel<<<64, 256>>>();
    xw_kernel<<<dim3(T_STEPS, 16), 256>>>(X, Wxh);
    dummy_kernel<<<1, 32>>>();     // position rnn_loop at the ncu capture slot
    rnn_loop<<<GCTA, RTHREADS>>>(Whh, bh, Y);
    att_q_kernel<<<BATCH, 256>>>(Y, QW, KW);
    att_scores_kernel<<<dim3(32, BATCH), 256>>>(Y);
    att_softmax_kernel<<<BATCH, 256>>>();
    att_ctx_kernel<<<dim3(8, BATCH), 256>>>(Y);
    att_ctx2_kernel<<<BATCH, 512>>>(out_c);
}

// round 16
// speedup vs baseline: 1.4438x; 1.4438x over previous
#include <cuda_runtime.h>
#include <math.h>

#define GCTA    128    // 16 groups x 8 CTAs
#define CPG     8      // CTAs per group
#define NGRP    16
#define RTHREADS 256
#define T_STEPS 2048
#define BATCH   32
#define HDIM    512
#define DIN     256

// ---- scratch (device globals; no allocation allowed) ----
__device__ float g_xw[(size_t)T_STEPS * BATCH * HDIM];   // [t][b][j], 134MB
__device__ unsigned long long g_hx[2][NGRP][CPG][128];   // h exchange, u64-dup
__device__ float g_qh[BATCH * HDIM];                     // KW @ Q0
__device__ float g_sc[BATCH * T_STEPS];                  // scores
__device__ float g_att[BATCH * T_STEPS];                 // softmax weights
__device__ float g_cpart[8][BATCH * HDIM];               // context partials
__device__ __align__(128) unsigned g_flag[GCTA * 32];    // per-CTA flags, 128B apart

// ---------------------------------------------------------------------------
__global__ void init_kernel() {
    int idx = blockIdx.x * blockDim.x + threadIdx.x;
    if (idx < GCTA) g_flag[idx * 32] = 0u;
}

__global__ void dummy_kernel() {}   // launch-position filler so ncu -s 5 lands on rnn_loop

// ---------------------------------------------------------------------------
// xw[t][b][j] = sum_d X[b][t][d] * Wxh[d][j]   (b-major so rnn reads coalesce)
__global__ __launch_bounds__(256) void xw_kernel(const float* __restrict__ X,
                                                 const float* __restrict__ Wxh) {
    __shared__ __align__(16) float Xs[128 * 33];  // [dl][b], padded
    __shared__ __align__(16) float Ws[128 * 32];  // [dl][jj]
    int t  = blockIdx.x;
    int j0 = blockIdx.y * 32;
    int tid = threadIdx.x;
    int warp = tid >> 5, lane = tid & 31;
    float acc0 = 0.f, acc1 = 0.f, acc2 = 0.f, acc3 = 0.f;

    for (int kp = 0; kp < 2; ++kp) {
        #pragma unroll
        for (int bb = 0; bb < 4; ++bb) {
            int b = warp * 4 + bb;
            const float* xp = X + ((size_t)b * T_STEPS + t) * DIN + kp * 128;
            #pragma unroll
            for (int it = 0; it < 4; ++it) {
                int dl = it * 32 + lane;
                Xs[dl * 33 + b] = xp[dl];
            }
        }
        for (int idx = tid; idx < 128 * 32; idx += 256) {
            int dl = idx >> 5, jj = idx & 31;
            Ws[idx] = Wxh[(size_t)(kp * 128 + dl) * HDIM + j0 + jj];
        }
        __syncthreads();
        // warp covers 4 b's, lane = j within the 32-block
        #pragma unroll 4
        for (int dl = 0; dl < 128; ++dl) {
            float wv = Ws[dl * 32 + lane];
            acc0 += Xs[dl * 33 + warp * 4 + 0] * wv;
            acc1 += Xs[dl * 33 + warp * 4 + 1] * wv;
            acc2 += Xs[dl * 33 + warp * 4 + 2] * wv;
            acc3 += Xs[dl * 33 + warp * 4 + 3] * wv;
        }
        __syncthreads();
    }
    float* op = g_xw + ((size_t)t * BATCH + warp * 4) * HDIM + j0 + lane;
    op[0]        = acc0;    // coalesced 128B per warp-store
    op[HDIM]     = acc1;
    op[2 * HDIM] = acc2;
    op[3 * HDIM] = acc3;
}

// ---------------------------------------------------------------------------
// Persistent recurrence: 16 INDEPENDENT groups of 8 CTAs (one batch pair per
// group — batches never couple, so no global barrier). CTA owns 64 j's for
// both batches; Whh slice lives in REGISTERS (64 u64 j-pair packed). Exchange:
// finisher stcg's its u64-dup chunk to g_hx + st.release flag; partners poll
// 7 flags and ldcg 7x1KB into smem. Max-over-8 straggler, not max-over-64.
__global__ __launch_bounds__(RTHREADS) void rnn_loop(const float* __restrict__ Whh,
                                                     const float* __restrict__ bh,
                                                     float* __restrict__ Y) {
    __shared__ __align__(16) unsigned long long hdup[2][2][HDIM]; // [par][b][i], 16KB
    __shared__ __align__(16) unsigned long long red[2][8][32];    // [b][warp][jp], 4KB

    int tid  = threadIdx.x;
    int warp = tid >> 5, lane = tid & 31;
    int grp  = blockIdx.x >> 3;
    int rank = blockIdx.x & 7;
    int jbase = rank * 64;
    int i0 = warp * 64;

    // ---- Whh slice -> registers: w64[k] = {W[i0+k][j0], W[i0+k][j0+1]} ----
    unsigned long long w64[64];
    {
        const float* wp = Whh + (size_t)i0 * HDIM + jbase + lane * 2;
        #pragma unroll
        for (int k = 0; k < 64; ++k) {
            float2 wv = *(const float2*)(wp + (size_t)k * HDIM);
            asm("mov.b64 %0, {%1, %2};" : "=l"(w64[k]) : "f"(wv.x), "f"(wv.y));
        }
    }

    // finisher mapping (tid < 128): fb = batch-in-pair, fj = j within slice
    int fb = tid >> 6, fj = tid & 63;
    float bias = (tid < 128) ? bh[jbase + fj] : 0.f;
    float xw_pref = (tid < 128)
        ? g_xw[((size_t)0 * BATCH + grp * 2 + fb) * HDIM + jbase + fj] : 0.f;
    unsigned* myflag = &g_flag[blockIdx.x * 32];

    // zero h(0)
    for (int idx = tid; idx < 2 * HDIM; idx += RTHREADS)
        hdup[0][idx >> 9][idx & 511] = 0ull;
    __syncthreads();

    for (int t = 0; t < T_STEPS; ++t) {
        int p = t & 1;
        if (t > 0) {
            // ---- detect 7 partners (lanes 0..7, skip self) ----
            if (tid < 8 && tid != rank) {
                unsigned* fp = &g_flag[(grp * CPG + tid) * 32];
                unsigned v, tgt = (unsigned)t;
                do { asm volatile("ld.relaxed.gpu.global.u32 %0, [%1];"
                                  : "=r"(v) : "l"(fp)); } while (v < tgt);
                asm volatile("fence.acq_rel.gpu;" ::: "memory");
            }
            __syncthreads();
            // ---- load 7 remote chunks (7 x 128 u64) into hdup[p] ----
            #pragma unroll
            for (int k = 0; k < 4; ++k) {
                int idx = tid + k * 256;
                if (idx < 896) {
                    int r7 = idx >> 7;
                    int rr = r7 + (r7 >= rank ? 1 : 0);
                    int e  = idx & 127;
                    unsigned long long v;
                    asm("ld.global.cg.b64 %0, [%1];" : "=l"(v)
                        : "l"(&g_hx[p][grp][rr][e]));
                    hdup[p][e >> 6][rr * 64 + (e & 63)] = v;
                }
            }
            __syncthreads();
        }

        // ---- compute: 64-i range per warp, j-pair per lane, both batches ----
        unsigned long long a0 = 0ull, a1 = 0ull;
        {
            const ulonglong2* h0 = (const ulonglong2*)&hdup[p][0][i0];
            const ulonglong2* h1 = (const ulonglong2*)&hdup[p][1][i0];
            #pragma unroll
            for (int k = 0; k < 32; ++k) {
                ulonglong2 A = h0[k];     // broadcast LDS.128
                ulonglong2 B = h1[k];
                asm("fma.rn.f32x2 %0, %1, %2, %0;" : "+l"(a0) : "l"(A.x), "l"(w64[2*k]));
                asm("fma.rn.f32x2 %0, %1, %2, %0;" : "+l"(a0) : "l"(A.y), "l"(w64[2*k+1]));
                asm("fma.rn.f32x2 %0, %1, %2, %0;" : "+l"(a1) : "l"(B.x), "l"(w64[2*k]));
                asm("fma.rn.f32x2 %0, %1, %2, %0;" : "+l"(a1) : "l"(B.y), "l"(w64[2*k+1]));
            }
        }
        red[0][warp][lane] = a0;
        red[1][warp][lane] = a1;
        __syncthreads();

        // ---- finish: reduce 8 warps, tanh, publish local + remote copy ----
        if (tid < 128) {
            float s = bias + xw_pref;
            #pragma unroll
            for (int ig = 0; ig < 8; ++ig)
                s += ((const float*)&red[fb][ig][fj >> 1])[fj & 1];   // conflict-free
            float hv = tanhf(s);
            unsigned long long dup;
            asm("mov.b64 %0, {%1, %1};" : "=l"(dup) : "f"(hv));
            hdup[p ^ 1][fb][jbase + fj] = dup;                        // own chunk local
            asm volatile("st.global.cg.b64 [%0], %1;"
                         :: "l"(&g_hx[p ^ 1][grp][rank][fb * 64 + fj]), "l"(dup));
        }
        __syncthreads();

        // ---- publish flag (release; syncthreads makes all stcg's cumulative) ----
        if (tid == 0) {
            unsigned ep = (unsigned)(t + 1);
            asm volatile("st.release.gpu.global.u32 [%0], %1;"
                         :: "l"(myflag), "r"(ep));
        }

        // ---- off-critical-path: Y output + xw prefetch (both coalesced) ----
        if (tid < 128) {
            float hv = ((const float*)&hdup[p ^ 1][fb][jbase + fj])[0];
            Y[((size_t)t * BATCH + grp * 2 + fb) * HDIM + jbase + fj] = hv;
            if (t + 1 < T_STEPS)
                xw_pref = g_xw[((size_t)(t + 1) * BATCH + grp * 2 + fb) * HDIM
                               + jbase + fj];
        }
    }
}

// ---------------------------------------------------------------------------
// Q0[b] = Y[T-1,b] @ QW ; Qh[b] = KW @ Q0[b]   (one CTA per b)
__global__ __launch_bounds__(256) void att_q_kernel(const float* __restrict__ Y,
                                                    const float* __restrict__ QW,
                                                    const float* __restrict__ KW) {
    __shared__ float yT[HDIM];
    __shared__ float q0s[DIN];
    int b = blockIdx.x, tid = threadIdx.x;
    for (int h = tid; h < HDIM; h += 256)
        yT[h] = Y[(size_t)(T_STEPS - 1) * BATCH * HDIM + (size_t)b * HDIM + h];
    __syncthreads();
    float s = 0.f;
    for (int h = 0; h < HDIM; ++h) s += yT[h] * QW[(size_t)h * DIN + tid];
    q0s[tid] = s;
    __syncthreads();
    for (int j = tid; j < HDIM; j += 256) {
        float s2 = 0.f;
        const float* kp = KW + (size_t)j * DIN;
        #pragma unroll 4
        for (int d = 0; d < DIN; ++d) s2 += kp[d] * q0s[d];
        g_qh[b * HDIM + j] = s2;
    }
}

// scores[b][t] = tanh( Y[t,b,:] . Qh[b,:] )
__global__ __launch_bounds__(256) void att_scores_kernel(const float* __restrict__ Y) {
    __shared__ float qh[HDIM];
    int b = blockIdx.y, t0 = blockIdx.x * 64, tid = threadIdx.x;
    for (int h = tid; h < HDIM; h += 256) qh[h] = g_qh[b * HDIM + h];
    __syncthreads();
    int warp = tid >> 5, lane = tid & 31;
    for (int tt = warp; tt < 64; tt += 8) {
        int t = t0 + tt;
        const float* yp = Y + (size_t)t * BATCH * HDIM + (size_t)b * HDIM;
        float s = 0.f;
        #pragma unroll
        for (int it = 0; it < 16; ++it) s += yp[it * 32 + lane] * qh[it * 32 + lane];
        #pragma unroll
        for (int off = 16; off > 0; off >>= 1) s += __shfl_xor_sync(0xffffffffu, s, off);
        if (lane == 0) g_sc[b * T_STEPS + t] = tanhf(s);
    }
}

__global__ __launch_bounds__(256) void att_softmax_kernel() {
    __shared__ float sred[256];
    int b = blockIdx.x, tid = threadIdx.x;
    const float* sp = g_sc + b * T_STEPS;
    float m = -1e30f;
    for (int t = tid; t < T_STEPS; t += 256) m = fmaxf(m, sp[t]);
    sred[tid] = m; __syncthreads();
    for (int o = 128; o > 0; o >>= 1) {
        if (tid < o) sred[tid] = fmaxf(sred[tid], sred[tid + o]);
        __syncthreads();
    }
    m = sred[0]; __syncthreads();
    float sum = 0.f;
    for (int t = tid; t < T_STEPS; t += 256) sum += expf(sp[t] - m);
    sred[tid] = sum; __syncthreads();
    for (int o = 128; o > 0; o >>= 1) {
        if (tid < o) sred[tid] += sred[tid + o];
        __syncthreads();
    }
    float inv = 1.f / sred[0];
    for (int t = tid; t < T_STEPS; t += 256)
        g_att[b * T_STEPS + t] = expf(sp[t] - m) * inv;
}

// c partials: grid (8 t-chunks, 32 b)
__global__ __launch_bounds__(256) void att_ctx_kernel(const float* __restrict__ Y) {
    __shared__ float As[256];
    int tc = blockIdx.x, b = blockIdx.y, tid = threadIdx.x;
    As[tid] = g_att[b * T_STEPS + tc * 256 + tid];
    __syncthreads();
    float acc0 = 0.f, acc1 = 0.f;
    for (int tt = 0; tt < 256; ++tt) {
        const float* yp = Y + (size_t)(tc * 256 + tt) * BATCH * HDIM + (size_t)b * HDIM;
        float a = As[tt];
        acc0 += a * yp[tid];
        acc1 += a * yp[tid + 256];
    }
    g_cpart[tc][b * HDIM + tid]        = acc0;
    g_cpart[tc][b * HDIM + tid + 256]  = acc1;
}

__global__ __launch_bounds__(512) void att_ctx2_kernel(float* __restrict__ out_c) {
    int b = blockIdx.x, tid = threadIdx.x;
    float s = 0.f;
    #pragma unroll
    for (int p = 0; p < 8; ++p) s += g_cpart[p][b * HDIM + tid];
    out_c[(size_t)b * HDIM + tid] = s;
}

// ---------------------------------------------------------------------------
extern "C" void kernel_launch(void* const* d_in, const int* in_sizes, int n_in,
                              void* d_out, int out_size) {
    const float* X   = (const float*)d_in[0];
    const float* Wxh = (const float*)d_in[1];
    const float* Whh = (const float*)d_in[2];
    const float* bh  = (const float*)d_in[3];
    const float* QW  = (const float*)d_in[4];
    const float* KW  = (const float*)d_in[5];
    float* Y = (float*)d_out;                                    // [T][B][H]
    float* out_c = Y + (size_t)T_STEPS * BATCH * HDIM;           // [B][H]

    init_kernel<<<64, 256>>>();
    xw_kernel<<<dim3(T_STEPS, 16), 256>>>(X, Wxh);
    dummy_kernel<<<1, 32>>>();     // position rnn_loop at the ncu capture slot
    rnn_loop<<<GCTA, RTHREADS>>>(Whh, bh, Y);
    att_q_kernel<<<BATCH, 256>>>(Y, QW, KW);
    att_scores_kernel<<<dim3(32, BATCH), 256>>>(Y);
    att_softmax_kernel<<<BATCH, 256>>>();
    att_ctx_kernel<<<dim3(8, BATCH), 256>>>(Y);
    att_ctx2_kernel<<<BATCH, 512>>>(out_c);
}

// round 17
// speedup vs baseline: 2.5986x; 1.7998x over previous
#include <cuda_runtime.h>
#include <math.h>

#define GCTA    128    // 16 groups x 8 CTAs
#define CPG     8      // CTAs per group
#define NGRP    16
#define RTHREADS 256
#define T_STEPS 2048
#define BATCH   32
#define HDIM    512
#define DIN     256

// ---- scratch (device globals; no allocation allowed) ----
__device__ float g_xw[(size_t)T_STEPS * BATCH * HDIM];   // [t][b][j], 134MB
// h exchange: u64 packets {hi: step tag, lo: f32 h bits}, ping-pong by parity
__device__ unsigned long long g_hx[2][NGRP][CPG][128];
__device__ float g_qh[BATCH * HDIM];                     // KW @ Q0
__device__ float g_sc[BATCH * T_STEPS];                  // scores
__device__ float g_att[BATCH * T_STEPS];                 // softmax weights
__device__ float g_cpart[8][BATCH * HDIM];               // context partials

// ---------------------------------------------------------------------------
// Clears exchange tags every graph replay (prevents stale-tag false validation).
__global__ void init_kernel() {
    int idx = blockIdx.x * blockDim.x + threadIdx.x;          // 16384 threads
    unsigned long long* p = &g_hx[0][0][0][0];
    int n = 2 * NGRP * CPG * 128;                             // 32768
    for (int i = idx; i < n; i += 16384) p[i] = 0xFFFFFFFF00000000ull;
}

__global__ void dummy_kernel() {}   // launch-position filler so ncu -s 5 lands on rnn_loop

// ---------------------------------------------------------------------------
// xw[t][b][j] = sum_d X[b][t][d] * Wxh[d][j]   (b-major so rnn reads coalesce)
__global__ __launch_bounds__(256) void xw_kernel(const float* __restrict__ X,
                                                 const float* __restrict__ Wxh) {
    __shared__ __align__(16) float Xs[128 * 33];  // [dl][b], padded
    __shared__ __align__(16) float Ws[128 * 32];  // [dl][jj]
    int t  = blockIdx.x;
    int j0 = blockIdx.y * 32;
    int tid = threadIdx.x;
    int warp = tid >> 5, lane = tid & 31;
    float acc0 = 0.f, acc1 = 0.f, acc2 = 0.f, acc3 = 0.f;

    for (int kp = 0; kp < 2; ++kp) {
        #pragma unroll
        for (int bb = 0; bb < 4; ++bb) {
            int b = warp * 4 + bb;
            const float* xp = X + ((size_t)b * T_STEPS + t) * DIN + kp * 128;
            #pragma unroll
            for (int it = 0; it < 4; ++it) {
                int dl = it * 32 + lane;
                Xs[dl * 33 + b] = xp[dl];
            }
        }
        for (int idx = tid; idx < 128 * 32; idx += 256) {
            int dl = idx >> 5, jj = idx & 31;
            Ws[idx] = Wxh[(size_t)(kp * 128 + dl) * HDIM + j0 + jj];
        }
        __syncthreads();
        // warp covers 4 b's, lane = j within the 32-block
        #pragma unroll 4
        for (int dl = 0; dl < 128; ++dl) {
            float wv = Ws[dl * 32 + lane];
            acc0 += Xs[dl * 33 + warp * 4 + 0] * wv;
            acc1 += Xs[dl * 33 + warp * 4 + 1] * wv;
            acc2 += Xs[dl * 33 + warp * 4 + 2] * wv;
            acc3 += Xs[dl * 33 + warp * 4 + 3] * wv;
        }
        __syncthreads();
    }
    float* op = g_xw + ((size_t)t * BATCH + warp * 4) * HDIM + j0 + lane;
    op[0]        = acc0;    // coalesced 128B per warp-store
    op[HDIM]     = acc1;
    op[2 * HDIM] = acc2;
    op[3 * HDIM] = acc3;
}

// ---------------------------------------------------------------------------
// Persistent recurrence: 16 independent groups of 8 CTAs (batch pair per
// group). Whh slice in REGISTERS. VALUE-CARRIED SYNC: exchanged h elements
// are u64 {tag=step, h}; consumers poll the data until tag==t. No flags, no
// fences, no ordering drains — each element is independently valid.
__global__ __launch_bounds__(RTHREADS) void rnn_loop(const float* __restrict__ Whh,
                                                     const float* __restrict__ bh,
                                                     float* __restrict__ Y) {
    __shared__ __align__(16) unsigned long long hdup[2][2][HDIM]; // [par][b][i], 16KB
    __shared__ __align__(16) unsigned long long red[2][8][32];    // [b][warp][jp], 4KB

    int tid  = threadIdx.x;
    int warp = tid >> 5, lane = tid & 31;
    int grp  = blockIdx.x >> 3;
    int rank = blockIdx.x & 7;
    int jbase = rank * 64;
    int i0 = warp * 64;

    // ---- Whh slice -> registers: w64[k] = {W[i0+k][j0], W[i0+k][j0+1]} ----
    unsigned long long w64[64];
    {
        const float* wp = Whh + (size_t)i0 * HDIM + jbase + lane * 2;
        #pragma unroll
        for (int k = 0; k < 64; ++k) {
            float2 wv = *(const float2*)(wp + (size_t)k * HDIM);
            asm("mov.b64 %0, {%1, %2};" : "=l"(w64[k]) : "f"(wv.x), "f"(wv.y));
        }
    }

    // finisher mapping (tid < 128): fb = batch-in-pair, fj = j within slice
    int fb = tid >> 6, fj = tid & 63;
    float bias = (tid < 128) ? bh[jbase + fj] : 0.f;
    float xw_pref = (tid < 128)
        ? g_xw[((size_t)0 * BATCH + grp * 2 + fb) * HDIM + jbase + fj] : 0.f;

    // zero h(0)
    for (int idx = tid; idx < 2 * HDIM; idx += RTHREADS)
        hdup[0][idx >> 9][idx & 511] = 0ull;
    __syncthreads();

    for (int t = 0; t < T_STEPS; ++t) {
        int p = t & 1;
        if (t > 0) {
            // ---- poll-load 7 remote chunks; each element self-validates ----
            unsigned tgt = (unsigned)t;
            #pragma unroll
            for (int k = 0; k < 4; ++k) {
                int idx = tid + k * 256;
                if (idx < 896) {
                    int r7 = idx >> 7;
                    int rr = r7 + (r7 >= rank ? 1 : 0);
                    int e  = idx & 127;
                    const unsigned long long* ap = &g_hx[p][grp][rr][e];
                    unsigned long long v;
                    do {
                        asm volatile("ld.relaxed.gpu.global.b64 %0, [%1];"
                                     : "=l"(v) : "l"(ap));
                    } while ((unsigned)(v >> 32) != tgt);
                    float hv = __uint_as_float((unsigned)v);
                    unsigned long long dup;
                    asm("mov.b64 %0, {%1, %1};" : "=l"(dup) : "f"(hv));
                    hdup[p][e >> 6][rr * 64 + (e & 63)] = dup;
                }
            }
        }
        __syncthreads();

        // ---- compute: 64-i range per warp, j-pair per lane, both batches ----
        unsigned long long a0 = 0ull, a1 = 0ull;
        {
            const ulonglong2* h0 = (const ulonglong2*)&hdup[p][0][i0];
            const ulonglong2* h1 = (const ulonglong2*)&hdup[p][1][i0];
            #pragma unroll
            for (int k = 0; k < 32; ++k) {
                ulonglong2 A = h0[k];     // broadcast LDS.128
                ulonglong2 B = h1[k];
                asm("fma.rn.f32x2 %0, %1, %2, %0;" : "+l"(a0) : "l"(A.x), "l"(w64[2*k]));
                asm("fma.rn.f32x2 %0, %1, %2, %0;" : "+l"(a0) : "l"(A.y), "l"(w64[2*k+1]));
                asm("fma.rn.f32x2 %0, %1, %2, %0;" : "+l"(a1) : "l"(B.x), "l"(w64[2*k]));
                asm("fma.rn.f32x2 %0, %1, %2, %0;" : "+l"(a1) : "l"(B.y), "l"(w64[2*k+1]));
            }
        }
        red[0][warp][lane] = a0;
        red[1][warp][lane] = a1;
        __syncthreads();

        // ---- finish: reduce, tanh, publish tagged packet (one store/thread) ----
        if (tid < 128) {
            float s = bias + xw_pref;
            #pragma unroll
            for (int ig = 0; ig < 8; ++ig)
                s += ((const float*)&red[fb][ig][fj >> 1])[fj & 1];   // conflict-free
            float hv = tanhf(s);
            unsigned long long dup;
            asm("mov.b64 %0, {%1, %1};" : "=l"(dup) : "f"(hv));
            hdup[p ^ 1][fb][jbase + fj] = dup;                        // own chunk local
            unsigned long long pkt =
                ((unsigned long long)(unsigned)(t + 1) << 32)
                | (unsigned long long)__float_as_uint(hv);
            asm volatile("st.relaxed.gpu.global.b64 [%0], %1;"
                         :: "l"(&g_hx[p ^ 1][grp][rank][fb * 64 + fj]), "l"(pkt));
            // off-critical-path: Y output + xw prefetch (both coalesced)
            Y[((size_t)t * BATCH + grp * 2 + fb) * HDIM + jbase + fj] = hv;
            if (t + 1 < T_STEPS)
                xw_pref = g_xw[((size_t)(t + 1) * BATCH + grp * 2 + fb) * HDIM
                               + jbase + fj];
        }
        __syncthreads();   // protect red + local hdup[p^1] before next iteration
    }
}

// ---------------------------------------------------------------------------
// Q0[b] = Y[T-1,b] @ QW ; Qh[b] = KW @ Q0[b]   (one CTA per b)
__global__ __launch_bounds__(256) void att_q_kernel(const float* __restrict__ Y,
                                                    const float* __restrict__ QW,
                                                    const float* __restrict__ KW) {
    __shared__ float yT[HDIM];
    __shared__ float q0s[DIN];
    int b = blockIdx.x, tid = threadIdx.x;
    for (int h = tid; h < HDIM; h += 256)
        yT[h] = Y[(size_t)(T_STEPS - 1) * BATCH * HDIM + (size_t)b * HDIM + h];
    __syncthreads();
    float s = 0.f;
    for (int h = 0; h < HDIM; ++h) s += yT[h] * QW[(size_t)h * DIN + tid];
    q0s[tid] = s;
    __syncthreads();
    for (int j = tid; j < HDIM; j += 256) {
        float s2 = 0.f;
        const float* kp = KW + (size_t)j * DIN;
        #pragma unroll 4
        for (int d = 0; d < DIN; ++d) s2 += kp[d] * q0s[d];
        g_qh[b * HDIM + j] = s2;
    }
}

// scores[b][t] = tanh( Y[t,b,:] . Qh[b,:] )
__global__ __launch_bounds__(256) void att_scores_kernel(const float* __restrict__ Y) {
    __shared__ float qh[HDIM];
    int b = blockIdx.y, t0 = blockIdx.x * 64, tid = threadIdx.x;
    for (int h = tid; h < HDIM; h += 256) qh[h] = g_qh[b * HDIM + h];
    __syncthreads();
    int warp = tid >> 5, lane = tid & 31;
    for (int tt = warp; tt < 64; tt += 8) {
        int t = t0 + tt;
        const float* yp = Y + (size_t)t * BATCH * HDIM + (size_t)b * HDIM;
        float s = 0.f;
        #pragma unroll
        for (int it = 0; it < 16; ++it) s += yp[it * 32 + lane] * qh[it * 32 + lane];
        #pragma unroll
        for (int off = 16; off > 0; off >>= 1) s += __shfl_xor_sync(0xffffffffu, s, off);
        if (lane == 0) g_sc[b * T_STEPS + t] = tanhf(s);
    }
}

__global__ __launch_bounds__(256) void att_softmax_kernel() {
    __shared__ float sred[256];
    int b = blockIdx.x, tid = threadIdx.x;
    const float* sp = g_sc + b * T_STEPS;
    float m = -1e30f;
    for (int t = tid; t < T_STEPS; t += 256) m = fmaxf(m, sp[t]);
    sred[tid] = m; __syncthreads();
    for (int o = 128; o > 0; o >>= 1) {
        if (tid < o) sred[tid] = fmaxf(sred[tid], sred[tid + o]);
        __syncthreads();
    }
    m = sred[0]; __syncthreads();
    float sum = 0.f;
    for (int t = tid; t < T_STEPS; t += 256) sum += expf(sp[t] - m);
    sred[tid] = sum; __syncthreads();
    for (int o = 128; o > 0; o >>= 1) {
        if (tid < o) sred[tid] += sred[tid + o];
        __syncthreads();
    }
    float inv = 1.f / sred[0];
    for (int t = tid; t < T_STEPS; t += 256)
        g_att[b * T_STEPS + t] = expf(sp[t] - m) * inv;
}

// c partials: grid (8 t-chunks, 32 b)
__global__ __launch_bounds__(256) void att_ctx_kernel(const float* __restrict__ Y) {
    __shared__ float As[256];
    int tc = blockIdx.x, b = blockIdx.y, tid = threadIdx.x;
    As[tid] = g_att[b * T_STEPS + tc * 256 + tid];
    __syncthreads();
    float acc0 = 0.f, acc1 = 0.f;
    for (int tt = 0; tt < 256; ++tt) {
        const float* yp = Y + (size_t)(tc * 256 + tt) * BATCH * HDIM + (size_t)b * HDIM;
        float a = As[tt];
        acc0 += a * yp[tid];
        acc1 += a * yp[tid + 256];
    }
    g_cpart[tc][b * HDIM + tid]        = acc0;
    g_cpart[tc][b * HDIM + tid + 256]  = acc1;
}

__global__ __launch_bounds__(512) void att_ctx2_kernel(float* __restrict__ out_c) {
    int b = blockIdx.x, tid = threadIdx.x;
    float s = 0.f;
    #pragma unroll
    for (int p = 0; p < 8; ++p) s += g_cpart[p][b * HDIM + tid];
    out_c[(size_t)b * HDIM + tid] = s;
}

// ---------------------------------------------------------------------------
extern "C" void kernel_launch(void* const* d_in, const int* in_sizes, int n_in,
                              void* d_out, int out_size) {
    const float* X   = (const float*)d_in[0];
    const float* Wxh = (const float*)d_in[1];
    const float* Whh = (const float*)d_in[2];
    const float* bh  = (const float*)d_in[3];
    const float* QW  = (const float*)d_in[4];
    const float* KW  = (const float*)d_in[5];
    float* Y = (float*)d_out;                                    // [T][B][H]
    float* out_c = Y + (size_t)T_STEPS * BATCH * HDIM;           // [B][H]

    init_kernel<<<64, 256>>>();
    xw_kernel<<<dim3(T_STEPS, 16), 256>>>(X, Wxh);
    dummy_kernel<<<1, 32>>>();     // position rnn_loop at the ncu capture slot
    rnn_loop<<<GCTA, RTHREADS>>>(Whh, bh, Y);
    att_q_kernel<<<BATCH, 256>>>(Y, QW, KW);
    att_scores_kernel<<<dim3(32, BATCH), 256>>>(Y);
    att_softmax_kernel<<<BATCH, 256>>>();
    att_ctx_kernel<<<dim3(8, BATCH), 256>>>(Y);
    att_ctx2_kernel<<<BATCH, 512>>>(out_c);
}